// round 1
// baseline (speedup 1.0000x reference)
#include <cuda_runtime.h>

// ---------------------------------------------------------------------------
// Conv_2259152798130: fused e3nn-style edge conv
//   h = relu(edge_attr @ W1 + b1)                 [E,64]
//   w = h @ W2 + b2                               [E,2304]  (never materialized)
//   out0[e,w] = N*(sum_u wa[u,w] x0[u] sh0 + 1/sqrt3 sum_{u,m} wb[u,w] x1[u,m] sh1[m])
//   out1[e,w,m] = N*(sh1[m] sum_u wc[u,w] x0[u] + sum_u wd[u,w] x1[u,m] sh0)
//   node out = residual + segment_mean(msg, dst)
// Inputs (metadata order): dst(i32), x_src, x_dst, sh, edge_attr,
//                          mlp_w1, mlp_b1, mlp_w2, mlp_b2, res_w0, res_w1
// ---------------------------------------------------------------------------

#define NN       10000      // nodes (fixed by problem)
#define OUT_DIM  80
#define NORM_V        0.14433756729740643f   // 1/sqrt(48)
#define INV_SQRT3_V   0.57735026918962576f
#define RSQRT32_V     0.17677669529663687f   // 1/sqrt(32)

__device__ float g_sums[NN * OUT_DIM];
__device__ float g_cnt[NN];

__global__ void zero_kernel(int n_nodes) {
    int i = blockIdx.x * blockDim.x + threadIdx.x;
    if (i < n_nodes * OUT_DIM) g_sums[i] = 0.0f;
    if (i < n_nodes) g_cnt[i] = 0.0f;
}

// ---------------------------------------------------------------------------
// Shared layout (floats), total 17216 floats = 68864 B (dynamic smem)
//   H_s   [64][68]   0      (h transposed: [k][e], pad 68 for alignment)
//   W2s   [65][64]   4352   (row 64 = b2 chunk)
//   x0_s  [64][33]   8512
//   y1_s  [64][17]   10624  (1/sqrt3 * sum_m x1*sh1)
//   z1_s  [64][49]   11712  (x1*sh0, [u*3+m])
//   sh0_s [64]       14848
//   sh1_s [64][3]    14912
//   W1_s  [32][64]   15104
//   dst_s [64] int   17152
// ---------------------------------------------------------------------------
#define SMEM_FLOATS 17216

__device__ __forceinline__ void stage_chunk(
    float* W2s, const float* __restrict__ w2, const float* __restrict__ b2,
    int j0, int tid)
{
    __syncthreads();   // protect previous chunk's readers
    const int srow = tid >> 4;            // 0..7
    const int scol = (tid & 15) << 2;     // 0,4,..,60
    const float* gp = w2 + srow * 2304 + j0 + scol;
#pragma unroll
    for (int r = 0; r < 8; r++)
        *(float4*)&W2s[(srow + r * 8) * 64 + scol] =
            *(const float4*)(gp + r * 8 * 2304);
    if (tid < 16)
        *(float4*)&W2s[4096 + tid * 4] = *(const float4*)&b2[j0 + tid * 4];
    __syncthreads();
}

// Register-tiled 8-edge x 4-col chunk GEMM: w[ee][q] = h[e,:]·W2s[:,q*16+tx] + b2
__device__ __forceinline__ void compute_w(
    const float* __restrict__ H_s, const float* __restrict__ W2s,
    int e0, int tx, float w[8][4])
{
#pragma unroll
    for (int ee = 0; ee < 8; ee++)
#pragma unroll
        for (int q = 0; q < 4; q++) w[ee][q] = 0.0f;

#pragma unroll 4
    for (int k = 0; k < 64; k++) {
        const float4 a0 = *(const float4*)&H_s[k * 68 + e0];
        const float4 a1 = *(const float4*)&H_s[k * 68 + e0 + 4];
        float b[4];
#pragma unroll
        for (int q = 0; q < 4; q++) b[q] = W2s[k * 64 + q * 16 + tx];
        const float a[8] = {a0.x, a0.y, a0.z, a0.w, a1.x, a1.y, a1.z, a1.w};
#pragma unroll
        for (int ee = 0; ee < 8; ee++)
#pragma unroll
            for (int q = 0; q < 4; q++)
                w[ee][q] = fmaf(a[ee], b[q], w[ee][q]);
    }
    // + b2 (staged as row 64)
#pragma unroll
    for (int q = 0; q < 4; q++) {
        const float bb = W2s[64 * 64 + q * 16 + tx];
#pragma unroll
        for (int ee = 0; ee < 8; ee++) w[ee][q] += bb;
    }
}

__global__ __launch_bounds__(128, 3) void edge_kernel(
    int E,
    const int*   __restrict__ dst,
    const float* __restrict__ x_src,
    const float* __restrict__ sh,
    const float* __restrict__ edge_attr,
    const float* __restrict__ w1,
    const float* __restrict__ b1,
    const float* __restrict__ w2,
    const float* __restrict__ b2)
{
    extern __shared__ float smem[];
    float* H_s   = smem;                   // [64][68]
    float* W2s   = smem + 4352;            // [65][64]
    float* x0_s  = smem + 8512;            // [64][33]
    float* y1_s  = smem + 10624;           // [64][17]
    float* z1_s  = smem + 11712;           // [64][49]
    float* sh0_s = smem + 14848;           // [64]
    float* sh1_s = smem + 14912;           // [64][3]
    float* W1_s  = smem + 15104;           // [32][64]
    int*   dst_s = (int*)(smem + 17152);   // [64]

    const int tid   = threadIdx.x;
    const int eBase = blockIdx.x * 64;
    const int e     = tid & 63;
    const int half  = tid >> 6;
    const int ge    = eBase + e;
    const bool valid = (ge < E);

    // ---- Phase 0: W1, per-edge features ----
    for (int i = tid; i < 512; i += 128)
        ((float4*)W1_s)[i] = ((const float4*)w1)[i];

    if (half == 0) {
        dst_s[e] = valid ? dst[ge] : 0;
        float s0 = 0.f, s1 = 0.f, s2 = 0.f, s3 = 0.f;
        if (valid) {
            const float4 shv = *(const float4*)&sh[ge * 4];
            s0 = shv.x; s1 = shv.y; s2 = shv.z; s3 = shv.w;
        }
        sh0_s[e] = s0;
        sh1_s[e * 3 + 0] = s1; sh1_s[e * 3 + 1] = s2; sh1_s[e * 3 + 2] = s3;
#pragma unroll
        for (int q = 0; q < 8; q++) {
            float4 v = valid ? ((const float4*)&x_src[ge * 80])[q]
                             : make_float4(0.f, 0.f, 0.f, 0.f);
            x0_s[e * 33 + q * 4 + 0] = v.x;
            x0_s[e * 33 + q * 4 + 1] = v.y;
            x0_s[e * 33 + q * 4 + 2] = v.z;
            x0_s[e * 33 + q * 4 + 3] = v.w;
        }
#pragma unroll
        for (int u = 0; u < 16; u++) {
            float a = 0.f, b = 0.f, c = 0.f;
            if (valid) {
                a = x_src[ge * 80 + 32 + u * 3 + 0];
                b = x_src[ge * 80 + 32 + u * 3 + 1];
                c = x_src[ge * 80 + 32 + u * 3 + 2];
            }
            y1_s[e * 17 + u] = INV_SQRT3_V * (a * s1 + b * s2 + c * s3);
            z1_s[e * 49 + u * 3 + 0] = a * s0;
            z1_s[e * 49 + u * 3 + 1] = b * s0;
            z1_s[e * 49 + u * 3 + 2] = c * s0;
        }
    }

    // layer-1 MLP: both halves compute 32 of the 64 h outputs for edge e
    float attr[32];
#pragma unroll
    for (int q = 0; q < 8; q++) {
        float4 v = valid ? ((const float4*)&edge_attr[ge * 32])[q]
                         : make_float4(0.f, 0.f, 0.f, 0.f);
        attr[q * 4 + 0] = v.x; attr[q * 4 + 1] = v.y;
        attr[q * 4 + 2] = v.z; attr[q * 4 + 3] = v.w;
    }
    __syncthreads();

#pragma unroll 2
    for (int jj = 0; jj < 32; jj++) {
        const int j = half * 32 + jj;
        float acc = __ldg(&b1[j]);
#pragma unroll
        for (int i = 0; i < 32; i++)
            acc = fmaf(attr[i], W1_s[i * 64 + j], acc);
        H_s[j * 68 + e] = fmaxf(acc, 0.0f);
    }
    __syncthreads();

    // ---- Main fused GEMM + contraction ----
    const int tx = tid & 15;       // column group
    const int ty = tid >> 4;       // edge group (8 edges each)
    const int e0 = ty * 8;

    float acc0[8][2];              // out0 partials: cols {tx, 16+tx}
#pragma unroll
    for (int ee = 0; ee < 8; ee++) { acc0[ee][0] = 0.f; acc0[ee][1] = 0.f; }

    // Region A (wa): j in [0,1024), u = 2*ch + (q>=2), col = (q&1)*16 + tx
#pragma unroll 1
    for (int ch = 0; ch < 16; ch++) {
        stage_chunk(W2s, w2, b2, ch * 64, tid);
        float w[8][4];
        compute_w(H_s, W2s, e0, tx, w);
#pragma unroll
        for (int ee = 0; ee < 8; ee++) {
            const int el = e0 + ee;
            const float s0  = sh0_s[el];
            const float y0a = x0_s[el * 33 + 2 * ch    ] * s0;
            const float y0b = x0_s[el * 33 + 2 * ch + 1] * s0;
            acc0[ee][0] += w[ee][0] * y0a + w[ee][2] * y0b;
            acc0[ee][1] += w[ee][1] * y0a + w[ee][3] * y0b;
        }
    }

    // Region C (wc): j in [1024,1536), u = 4*ch + q, col = tx (tx<16)
    float cacc[8];
#pragma unroll
    for (int ee = 0; ee < 8; ee++) cacc[ee] = 0.f;
#pragma unroll 1
    for (int ch = 0; ch < 8; ch++) {
        stage_chunk(W2s, w2, b2, 1024 + ch * 64, tid);
        float w[8][4];
        compute_w(H_s, W2s, e0, tx, w);
#pragma unroll
        for (int ee = 0; ee < 8; ee++) {
            const int el = e0 + ee;
            cacc[ee] += w[ee][0] * x0_s[el * 33 + 4 * ch    ]
                      + w[ee][1] * x0_s[el * 33 + 4 * ch + 1]
                      + w[ee][2] * x0_s[el * 33 + 4 * ch + 2]
                      + w[ee][3] * x0_s[el * 33 + 4 * ch + 3];
        }
    }

    // Region D (wd): j in [1536,1792), u = 4*ch + q, col = tx
    float dacc[8][3];
#pragma unroll
    for (int ee = 0; ee < 8; ee++) {
        dacc[ee][0] = 0.f; dacc[ee][1] = 0.f; dacc[ee][2] = 0.f;
    }
#pragma unroll 1
    for (int ch = 0; ch < 4; ch++) {
        stage_chunk(W2s, w2, b2, 1536 + ch * 64, tid);
        float w[8][4];
        compute_w(H_s, W2s, e0, tx, w);
#pragma unroll
        for (int ee = 0; ee < 8; ee++) {
            const int el = e0 + ee;
#pragma unroll
            for (int q = 0; q < 4; q++) {
                const int u = 4 * ch + q;
                dacc[ee][0] = fmaf(w[ee][q], z1_s[el * 49 + u * 3    ], dacc[ee][0]);
                dacc[ee][1] = fmaf(w[ee][q], z1_s[el * 49 + u * 3 + 1], dacc[ee][1]);
                dacc[ee][2] = fmaf(w[ee][q], z1_s[el * 49 + u * 3 + 2], dacc[ee][2]);
            }
        }
    }

    // out1 writeout: out[32 + w*3 + m], w = tx; merged c & d (same owner thread)
#pragma unroll
    for (int ee = 0; ee < 8; ee++) {
        const int el = e0 + ee;
        if (eBase + el < E) {
            const int node = dst_s[el];
#pragma unroll
            for (int m = 0; m < 3; m++) {
                const float v = NORM_V * (sh1_s[el * 3 + m] * cacc[ee] + dacc[ee][m]);
                atomicAdd(&g_sums[node * 80 + 32 + tx * 3 + m], v);
            }
        }
    }

    // Region B (wb): j in [1792,2304), u = 2*ch + (q>=2), col = (q&1)*16 + tx
#pragma unroll 1
    for (int ch = 0; ch < 8; ch++) {
        stage_chunk(W2s, w2, b2, 1792 + ch * 64, tid);
        float w[8][4];
        compute_w(H_s, W2s, e0, tx, w);
#pragma unroll
        for (int ee = 0; ee < 8; ee++) {
            const int el = e0 + ee;
            const float y1a = y1_s[el * 17 + 2 * ch    ];
            const float y1b = y1_s[el * 17 + 2 * ch + 1];
            acc0[ee][0] += w[ee][0] * y1a + w[ee][2] * y1b;
            acc0[ee][1] += w[ee][1] * y1a + w[ee][3] * y1b;
        }
    }

    // out0 writeout + edge count
#pragma unroll
    for (int ee = 0; ee < 8; ee++) {
        const int el = e0 + ee;
        if (eBase + el < E) {
            const int node = dst_s[el];
            atomicAdd(&g_sums[node * 80 + tx],      NORM_V * acc0[ee][0]);
            atomicAdd(&g_sums[node * 80 + 16 + tx], NORM_V * acc0[ee][1]);
            if (tx == 0) atomicAdd(&g_cnt[node], 1.0f);
        }
    }
}

// ---------------------------------------------------------------------------
// residual + mean
// ---------------------------------------------------------------------------
__global__ void final_kernel(
    int n_nodes,
    const float* __restrict__ x_dst,
    const float* __restrict__ rw0,
    const float* __restrict__ rw1,
    float* __restrict__ out)
{
    const int idx = blockIdx.x * blockDim.x + threadIdx.x;
    if (idx >= n_nodes * 80) return;
    const int n = idx / 80;
    const int j = idx - n * 80;
    float res;
    if (j < 32) {
        float acc = 0.f;
#pragma unroll
        for (int u = 0; u < 32; u++)
            acc = fmaf(x_dst[n * 80 + u], rw0[u * 32 + j], acc);
        res = acc * RSQRT32_V;
    } else {
        const int w = (j - 32) / 3;
        const int m = (j - 32) - 3 * w;
        float acc = 0.f;
#pragma unroll
        for (int u = 0; u < 16; u++)
            acc = fmaf(x_dst[n * 80 + 32 + u * 3 + m], rw1[u * 16 + w], acc);
        res = acc * 0.25f;
    }
    const float c = fmaxf(g_cnt[n], 1.0f);
    out[idx] = res + g_sums[idx] / c;
}

// ---------------------------------------------------------------------------
extern "C" void kernel_launch(void* const* d_in, const int* in_sizes, int n_in,
                              void* d_out, int out_size)
{
    const int*   dst       = (const int*)  d_in[0];
    const float* x_src     = (const float*)d_in[1];
    const float* x_dst     = (const float*)d_in[2];
    const float* sh        = (const float*)d_in[3];
    const float* edge_attr = (const float*)d_in[4];
    const float* w1        = (const float*)d_in[5];
    const float* b1        = (const float*)d_in[6];
    const float* w2        = (const float*)d_in[7];
    const float* b2        = (const float*)d_in[8];
    const float* rw0       = (const float*)d_in[9];
    const float* rw1       = (const float*)d_in[10];
    float* out = (float*)d_out;

    const int E       = in_sizes[0];
    const int n_nodes = in_sizes[2] / OUT_DIM;

    cudaFuncSetAttribute(edge_kernel,
                         cudaFuncAttributeMaxDynamicSharedMemorySize,
                         SMEM_FLOATS * 4);

    zero_kernel<<<(n_nodes * OUT_DIM + 255) / 256, 256>>>(n_nodes);
    edge_kernel<<<(E + 63) / 64, 128, SMEM_FLOATS * 4>>>(
        E, dst, x_src, sh, edge_attr, w1, b1, w2, b2);
    final_kernel<<<(n_nodes * OUT_DIM + 127) / 128, 128>>>(
        n_nodes, x_dst, rw0, rw1, out);
}

// round 2
// speedup vs baseline: 2.5814x; 2.5814x over previous
#include <cuda_runtime.h>

// ---------------------------------------------------------------------------
// Conv_2259152798130 — fused e3nn edge conv, tf32 tensor-core version.
//   h = relu(edge_attr @ W1 + b1)          [E,64]
//   w = h @ W2 + b2                        [E,2304]  (tf32 mma, never stored)
//   region-aware contraction -> msg[E,80] -> atomic segment sum
//   out = residual + segment_mean
// ---------------------------------------------------------------------------

#define NN       10000
#define OUT_DIM  80
#define NORM_V        0.14433756729740643f   // 1/sqrt(48)
#define INV_SQRT3_V   0.57735026918962576f
#define RSQRT32_V     0.17677669529663687f   // 1/sqrt(32)

__device__ float g_sums[NN * OUT_DIM];
__device__ float g_cnt[NN];

__global__ void zero_kernel(int n_nodes) {
    int i = blockIdx.x * blockDim.x + threadIdx.x;
    if (i < n_nodes * OUT_DIM) g_sums[i] = 0.0f;
    if (i < n_nodes) g_cnt[i] = 0.0f;
}

__device__ __forceinline__ float ftf32(float x) {
    float r;
    asm("cvt.rna.tf32.f32 %0, %1;" : "=f"(r) : "f"(x));
    return r;
}

// mma.sync m16n8k8 tf32: D = A*B + D  (A row-major, B col-major, fp32 accum)
__device__ __forceinline__ void mma_tf32(float c[4], const unsigned a[4],
                                         unsigned b0, unsigned b1) {
    asm volatile(
        "mma.sync.aligned.m16n8k8.row.col.f32.tf32.tf32.f32 "
        "{%0,%1,%2,%3}, {%4,%5,%6,%7}, {%8,%9}, {%0,%1,%2,%3};"
        : "+f"(c[0]), "+f"(c[1]), "+f"(c[2]), "+f"(c[3])
        : "r"(a[0]), "r"(a[1]), "r"(a[2]), "r"(a[3]), "r"(b0), "r"(b1));
}

// ---------------------------------------------------------------------------
// Shared layout (floats), 128 edges/block:
//   H_s   [128][68]  @ 0      (h, tf32-rounded, row-major [e][k])
//   W2s   [64][64]   @ 8704   (tf32, swizzled col ^= (k&3)<<3; W1 staged here
//                              during phase 0: needs 2048 <= 4096)
//   b2s   [64]       @ 12800
//   x0_s  [128][33]  @ 12864
//   y1_s  [128][17]  @ 17088  (1/sqrt3 * sum_m x1*sh1)
//   z1_s  [128][49]  @ 19264  (x1*sh0)
//   sh0_s [128]      @ 25536
//   sh1_s [128][3]   @ 25664
//   dst_s [128] int  @ 26048
// ---------------------------------------------------------------------------
#define SMEM_FLOATS 26176

__device__ __forceinline__ void stage_chunk(
    float* W2s, float* b2s,
    const float* __restrict__ w2, const float* __restrict__ b2,
    int j0, int tid)
{
    __syncthreads();   // protect previous chunk's readers
    const int srow = tid >> 4;            // 0..15 (k row)
    const int scol = (tid & 15) << 2;     // 0,4,..,60
    const float* gp = w2 + srow * 2304 + j0 + scol;
#pragma unroll
    for (int r = 0; r < 4; r++) {
        const int k = srow + r * 16;
        float4 v = *(const float4*)(gp + r * 16 * 2304);
        v.x = ftf32(v.x); v.y = ftf32(v.y); v.z = ftf32(v.z); v.w = ftf32(v.w);
        *(float4*)&W2s[k * 64 + (scol ^ ((k & 3) << 3))] = v;
    }
    if (tid < 16)
        *(float4*)&b2s[tid * 4] = *(const float4*)&b2[j0 + tid * 4];
    __syncthreads();
}

// Compute one half-chunk (4 n-tiles) of w = h@W2+b2 into cbuf[4][4].
__device__ __forceinline__ void compute_w_half(
    const float* __restrict__ W2s, const float* __restrict__ b2s,
    const unsigned a[8][4], int h2, int gid, int qd, float cbuf[4][4])
{
#pragma unroll
    for (int n = 0; n < 4; n++)
#pragma unroll
        for (int j = 0; j < 4; j++) cbuf[n][j] = 0.0f;

    const unsigned* W2u = (const unsigned*)W2s;
    const int swz = qd << 3;
#pragma unroll
    for (int ks = 0; ks < 8; ks++) {
        const int k0 = ks * 8 + qd;
#pragma unroll
        for (int n = 0; n < 4; n++) {
            const int nt  = h2 * 4 + n;
            const int col = (nt * 8 + gid) ^ swz;
            const unsigned b0 = W2u[k0 * 64 + col];
            const unsigned b1 = W2u[(k0 + 4) * 64 + col];
            mma_tf32(cbuf[n], a[ks], b0, b1);
        }
    }
    // + bias
#pragma unroll
    for (int n = 0; n < 4; n++) {
        const int nt = h2 * 4 + n;
        const float bb0 = b2s[nt * 8 + 2 * qd];
        const float bb1 = b2s[nt * 8 + 2 * qd + 1];
        cbuf[n][0] += bb0; cbuf[n][1] += bb1;
        cbuf[n][2] += bb0; cbuf[n][3] += bb1;
    }
}

__global__ __launch_bounds__(256, 2) void edge_kernel(
    int E,
    const int*   __restrict__ dst,
    const float* __restrict__ x_src,
    const float* __restrict__ sh,
    const float* __restrict__ edge_attr,
    const float* __restrict__ w1,
    const float* __restrict__ b1,
    const float* __restrict__ w2,
    const float* __restrict__ b2)
{
    extern __shared__ float smem[];
    float* H_s   = smem;                    // [128][68]
    float* W2s   = smem + 8704;             // [64][64] (W1 in phase 0)
    float* b2s   = smem + 12800;            // [64]
    float* x0_s  = smem + 12864;            // [128][33]
    float* y1_s  = smem + 17088;            // [128][17]
    float* z1_s  = smem + 19264;            // [128][49]
    float* sh0_s = smem + 25536;            // [128]
    float* sh1_s = smem + 25664;            // [128][3]
    int*   dst_s = (int*)(smem + 26048);    // [128]
    float* W1_s  = W2s;                     // phase-0 alias

    const int tid   = threadIdx.x;
    const int eBase = blockIdx.x * 128;
    const int e     = tid & 127;
    const int half  = tid >> 7;
    const int ge    = eBase + e;
    const bool valid = (ge < E);

    // ---- Phase 0: stage W1, per-edge features ----
    for (int i = tid; i < 512; i += 256)
        ((float4*)W1_s)[i] = ((const float4*)w1)[i];

    if (half == 0) {   // tid == e, one thread per edge
        dst_s[e] = valid ? dst[ge] : 0;
        float s0 = 0.f, s1 = 0.f, s2 = 0.f, s3 = 0.f;
        if (valid) {
            const float4 shv = *(const float4*)&sh[ge * 4];
            s0 = shv.x; s1 = shv.y; s2 = shv.z; s3 = shv.w;
        }
        sh0_s[e] = s0;
        sh1_s[e * 3 + 0] = s1; sh1_s[e * 3 + 1] = s2; sh1_s[e * 3 + 2] = s3;
#pragma unroll
        for (int q = 0; q < 8; q++) {
            float4 v = valid ? ((const float4*)&x_src[ge * 80])[q]
                             : make_float4(0.f, 0.f, 0.f, 0.f);
            x0_s[e * 33 + q * 4 + 0] = v.x;
            x0_s[e * 33 + q * 4 + 1] = v.y;
            x0_s[e * 33 + q * 4 + 2] = v.z;
            x0_s[e * 33 + q * 4 + 3] = v.w;
        }
#pragma unroll
        for (int u = 0; u < 16; u++) {
            float a = 0.f, b = 0.f, c = 0.f;
            if (valid) {
                a = x_src[ge * 80 + 32 + u * 3 + 0];
                b = x_src[ge * 80 + 32 + u * 3 + 1];
                c = x_src[ge * 80 + 32 + u * 3 + 2];
            }
            y1_s[e * 17 + u] = INV_SQRT3_V * (a * s1 + b * s2 + c * s3);
            z1_s[e * 49 + u * 3 + 0] = a * s0;
            z1_s[e * 49 + u * 3 + 1] = b * s0;
            z1_s[e * 49 + u * 3 + 2] = c * s0;
        }
    }

    // layer-1 MLP: each of the 2 halves computes 32 of 64 h outputs of edge e
    float attr[32];
#pragma unroll
    for (int q = 0; q < 8; q++) {
        float4 v = valid ? ((const float4*)&edge_attr[ge * 32])[q]
                         : make_float4(0.f, 0.f, 0.f, 0.f);
        attr[q * 4 + 0] = v.x; attr[q * 4 + 1] = v.y;
        attr[q * 4 + 2] = v.z; attr[q * 4 + 3] = v.w;
    }
    __syncthreads();

#pragma unroll 2
    for (int jj = 0; jj < 32; jj++) {
        const int j = half * 32 + jj;
        float acc = __ldg(&b1[j]);
#pragma unroll
        for (int i = 0; i < 32; i++)
            acc = fmaf(attr[i], W1_s[i * 64 + j], acc);
        H_s[e * 68 + j] = ftf32(fmaxf(acc, 0.0f));
    }
    __syncthreads();

    // ---- A fragments (chunk-invariant): 8 k-steps x 4 regs ----
    const int lane = tid & 31;
    const int warp = tid >> 5;          // 0..7, covers edges warp*16..+15
    const int gid  = lane >> 2;         // 0..7
    const int qd   = lane & 3;          // 0..3
    const int er0  = warp * 16 + gid;
    const int er1  = er0 + 8;

    unsigned a[8][4];
#pragma unroll
    for (int ks = 0; ks < 8; ks++) {
        a[ks][0] = __float_as_uint(H_s[er0 * 68 + ks * 8 + qd]);
        a[ks][1] = __float_as_uint(H_s[er1 * 68 + ks * 8 + qd]);
        a[ks][2] = __float_as_uint(H_s[er0 * 68 + ks * 8 + qd + 4]);
        a[ks][3] = __float_as_uint(H_s[er1 * 68 + ks * 8 + qd + 4]);
    }

    float acc0[2][4][2];                 // out0: [row][ntile 0..3][col pair]
#pragma unroll
    for (int r = 0; r < 2; r++)
#pragma unroll
        for (int n = 0; n < 4; n++) { acc0[r][n][0] = 0.f; acc0[r][n][1] = 0.f; }

    // ================= Region A (wa): chunks 0..15, u = 2ch + (col>=32) =====
#pragma unroll 1
    for (int ch = 0; ch < 16; ch++) {
        stage_chunk(W2s, b2s, w2, b2, ch * 64, tid);
#pragma unroll
        for (int h2 = 0; h2 < 2; h2++) {
            float c[4][4];
            compute_w_half(W2s, b2s, a, h2, gid, qd, c);
#pragma unroll
            for (int r = 0; r < 2; r++) {
                const int er = r ? er1 : er0;
                const float y = x0_s[er * 33 + 2 * ch + h2] * sh0_s[er];
#pragma unroll
                for (int n = 0; n < 4; n++) {
                    acc0[r][n][0] = fmaf(c[n][r * 2 + 0], y, acc0[r][n][0]);
                    acc0[r][n][1] = fmaf(c[n][r * 2 + 1], y, acc0[r][n][1]);
                }
            }
        }
    }

    // ================= Region C (wc): chunks 16..23, u = 4ch + nt>>1 ========
    float cacc[2][2][2];
#pragma unroll
    for (int r = 0; r < 2; r++)
#pragma unroll
        for (int p = 0; p < 2; p++) { cacc[r][p][0] = 0.f; cacc[r][p][1] = 0.f; }
#pragma unroll 1
    for (int ch = 0; ch < 8; ch++) {
        stage_chunk(W2s, b2s, w2, b2, 1024 + ch * 64, tid);
#pragma unroll
        for (int h2 = 0; h2 < 2; h2++) {
            float c[4][4];
            compute_w_half(W2s, b2s, a, h2, gid, qd, c);
#pragma unroll
            for (int r = 0; r < 2; r++) {
                const int er = r ? er1 : er0;
                const float xa = x0_s[er * 33 + 4 * ch + h2 * 2 + 0];
                const float xb = x0_s[er * 33 + 4 * ch + h2 * 2 + 1];
#pragma unroll
                for (int p = 0; p < 2; p++) {
                    cacc[r][p][0] = fmaf(c[p][r * 2 + 0], xa,
                                    fmaf(c[2 + p][r * 2 + 0], xb, cacc[r][p][0]));
                    cacc[r][p][1] = fmaf(c[p][r * 2 + 1], xa,
                                    fmaf(c[2 + p][r * 2 + 1], xb, cacc[r][p][1]));
                }
            }
        }
    }

    // ================= Region D (wd): chunks 24..27, u = 4ch + nt>>1 ========
    float dacc[2][2][2][3];
#pragma unroll
    for (int r = 0; r < 2; r++)
#pragma unroll
        for (int p = 0; p < 2; p++)
#pragma unroll
            for (int j = 0; j < 2; j++) {
                dacc[r][p][j][0] = 0.f; dacc[r][p][j][1] = 0.f; dacc[r][p][j][2] = 0.f;
            }
#pragma unroll 1
    for (int ch = 0; ch < 4; ch++) {
        stage_chunk(W2s, b2s, w2, b2, 1536 + ch * 64, tid);
#pragma unroll
        for (int h2 = 0; h2 < 2; h2++) {
            float c[4][4];
            compute_w_half(W2s, b2s, a, h2, gid, qd, c);
#pragma unroll
            for (int r = 0; r < 2; r++) {
                const int er = r ? er1 : er0;
#pragma unroll
                for (int t = 0; t < 2; t++) {       // local u pair
                    const int u = 4 * ch + h2 * 2 + t;
                    const float za = z1_s[er * 49 + u * 3 + 0];
                    const float zb = z1_s[er * 49 + u * 3 + 1];
                    const float zc = z1_s[er * 49 + u * 3 + 2];
#pragma unroll
                    for (int p = 0; p < 2; p++) {
                        const int n = t * 2 + p;    // nt within half
#pragma unroll
                        for (int j = 0; j < 2; j++) {
                            const float wv = c[n][r * 2 + j];
                            dacc[r][p][j][0] = fmaf(wv, za, dacc[r][p][j][0]);
                            dacc[r][p][j][1] = fmaf(wv, zb, dacc[r][p][j][1]);
                            dacc[r][p][j][2] = fmaf(wv, zc, dacc[r][p][j][2]);
                        }
                    }
                }
            }
        }
    }

    // ---- out1 writeout (cols 32..79): v = p*8 + 2*qd + j ----
#pragma unroll
    for (int r = 0; r < 2; r++) {
        const int er = r ? er1 : er0;
        if (eBase + er < E) {
            const int node = dst_s[er];
            const float s1v = sh1_s[er * 3 + 0];
            const float s2v = sh1_s[er * 3 + 1];
            const float s3v = sh1_s[er * 3 + 2];
#pragma unroll
            for (int p = 0; p < 2; p++)
#pragma unroll
                for (int j = 0; j < 2; j++) {
                    const int v = p * 8 + 2 * qd + j;
                    const float cc = cacc[r][p][j];
                    atomicAdd(&g_sums[node * 80 + 32 + v * 3 + 0],
                              NORM_V * (s1v * cc + dacc[r][p][j][0]));
                    atomicAdd(&g_sums[node * 80 + 32 + v * 3 + 1],
                              NORM_V * (s2v * cc + dacc[r][p][j][1]));
                    atomicAdd(&g_sums[node * 80 + 32 + v * 3 + 2],
                              NORM_V * (s3v * cc + dacc[r][p][j][2]));
                }
        }
    }

    // ================= Region B (wb): chunks 28..35, u = 2ch + (col>=32) ====
#pragma unroll 1
    for (int ch = 0; ch < 8; ch++) {
        stage_chunk(W2s, b2s, w2, b2, 1792 + ch * 64, tid);
#pragma unroll
        for (int h2 = 0; h2 < 2; h2++) {
            float c[4][4];
            compute_w_half(W2s, b2s, a, h2, gid, qd, c);
#pragma unroll
            for (int r = 0; r < 2; r++) {
                const int er = r ? er1 : er0;
                const float y = y1_s[er * 17 + 2 * ch + h2];
#pragma unroll
                for (int n = 0; n < 4; n++) {
                    acc0[r][n][0] = fmaf(c[n][r * 2 + 0], y, acc0[r][n][0]);
                    acc0[r][n][1] = fmaf(c[n][r * 2 + 1], y, acc0[r][n][1]);
                }
            }
        }
    }

    // ---- out0 writeout (cols 0..31) + count ----
#pragma unroll
    for (int r = 0; r < 2; r++) {
        const int er = r ? er1 : er0;
        if (eBase + er < E) {
            const int node = dst_s[er];
#pragma unroll
            for (int n = 0; n < 4; n++) {
                const int col = n * 8 + 2 * qd;
                atomicAdd(&g_sums[node * 80 + col],     NORM_V * acc0[r][n][0]);
                atomicAdd(&g_sums[node * 80 + col + 1], NORM_V * acc0[r][n][1]);
            }
            if (qd == 0) atomicAdd(&g_cnt[node], 1.0f);
        }
    }
}

// ---------------------------------------------------------------------------
// residual + mean
// ---------------------------------------------------------------------------
__global__ void final_kernel(
    int n_nodes,
    const float* __restrict__ x_dst,
    const float* __restrict__ rw0,
    const float* __restrict__ rw1,
    float* __restrict__ out)
{
    const int idx = blockIdx.x * blockDim.x + threadIdx.x;
    if (idx >= n_nodes * 80) return;
    const int n = idx / 80;
    const int j = idx - n * 80;
    float res;
    if (j < 32) {
        float acc = 0.f;
#pragma unroll
        for (int u = 0; u < 32; u++)
            acc = fmaf(x_dst[n * 80 + u], rw0[u * 32 + j], acc);
        res = acc * RSQRT32_V;
    } else {
        const int w = (j - 32) / 3;
        const int m = (j - 32) - 3 * w;
        float acc = 0.f;
#pragma unroll
        for (int u = 0; u < 16; u++)
            acc = fmaf(x_dst[n * 80 + 32 + u * 3 + m], rw1[u * 16 + w], acc);
        res = acc * 0.25f;
    }
    const float c = fmaxf(g_cnt[n], 1.0f);
    out[idx] = res + g_sums[idx] / c;
}

// ---------------------------------------------------------------------------
extern "C" void kernel_launch(void* const* d_in, const int* in_sizes, int n_in,
                              void* d_out, int out_size)
{
    const int*   dst       = (const int*)  d_in[0];
    const float* x_src     = (const float*)d_in[1];
    const float* x_dst     = (const float*)d_in[2];
    const float* sh        = (const float*)d_in[3];
    const float* edge_attr = (const float*)d_in[4];
    const float* w1        = (const float*)d_in[5];
    const float* b1        = (const float*)d_in[6];
    const float* w2        = (const float*)d_in[7];
    const float* b2        = (const float*)d_in[8];
    const float* rw0       = (const float*)d_in[9];
    const float* rw1       = (const float*)d_in[10];
    float* out = (float*)d_out;

    const int E       = in_sizes[0];
    const int n_nodes = in_sizes[2] / OUT_DIM;

    cudaFuncSetAttribute(edge_kernel,
                         cudaFuncAttributeMaxDynamicSharedMemorySize,
                         SMEM_FLOATS * 4);

    zero_kernel<<<(n_nodes * OUT_DIM + 255) / 256, 256>>>(n_nodes);
    edge_kernel<<<(E + 127) / 128, 256, SMEM_FLOATS * 4>>>(
        E, dst, x_src, sh, edge_attr, w1, b1, w2, b2);
    final_kernel<<<(n_nodes * OUT_DIM + 127) / 128, 128>>>(
        n_nodes, x_dst, rw0, rw1, out);
}